// round 14
// baseline (speedup 1.0000x reference)
#include <cuda_runtime.h>

#define BB 16
#define HH 2048
#define WW 2048
#define SS 5000
#define TOTAL (BB * SS)            // 80000 stations
#define THREADS 320                // 10 warps; 250 * 320 == 80000 exactly
#define NBLK (TOTAL / THREADS)     // 250 blocks
#define NWARP (THREADS / 32)       // 10

__device__ float        g_partials[NBLK];
__device__ unsigned int g_count;   // zero at module load; re-armed by last block

__device__ __forceinline__ unsigned atomic_inc_acqrel(unsigned int* p) {
    unsigned old;
    asm volatile("atom.acq_rel.gpu.global.add.u32 %0, [%1], %2;"
                 : "=r"(old) : "l"(p), "r"(1u) : "memory");
    return old;
}

// L2 evict_last via cache-policy operand (the immediate-qualifier form is
// restricted to 256-bit loads on this toolchain).
__device__ __forceinline__ unsigned long long make_evict_last_policy() {
    unsigned long long pol;
    asm("createpolicy.fractional.L2::evict_last.b64 %0, 1.0;" : "=l"(pol));
    return pol;
}
__device__ __forceinline__ float4 ldg_el_f4(const float4* p, unsigned long long pol) {
    float4 v;
    asm("ld.global.nc.L2::cache_hint.v4.f32 {%0,%1,%2,%3}, [%4], %5;"
        : "=f"(v.x), "=f"(v.y), "=f"(v.z), "=f"(v.w) : "l"(p), "l"(pol));
    return v;
}
__device__ __forceinline__ int2 ldg_el_i2(const int2* p, unsigned long long pol) {
    int2 v;
    asm("ld.global.nc.L2::cache_hint.v2.s32 {%0,%1}, [%2], %3;"
        : "=r"(v.x), "=r"(v.y) : "l"(p), "l"(pol));
    return v;
}
__device__ __forceinline__ float ldg_el_f(const float* p, unsigned long long pol) {
    float v;
    asm("ld.global.nc.L2::cache_hint.f32 %0, [%1], %2;"
        : "=f"(v) : "l"(p), "l"(pol));
    return v;
}

__device__ __forceinline__ float row_sum3(const float* rowbase, int a4, int off,
                                          unsigned long long pol) {
    const float4* r = reinterpret_cast<const float4*>(rowbase);
    float4 v0 = ldg_el_f4(r + a4, pol);
    float4 v1 = make_float4(0.f, 0.f, 0.f, 0.f);
    if (off >= 2) v1 = ldg_el_f4(r + a4 + 1, pol);   // predicated second load
    float s;
    if      (off == 0) s = v0.x + v0.y + v0.z;
    else if (off == 1) s = v0.y + v0.z + v0.w;
    else if (off == 2) s = v0.z + v0.w + v1.x;
    else               s = v0.w + v1.x + v1.y;
    return s;
}

__device__ __forceinline__ float warp_reduce(float v) {
    #pragma unroll
    for (int off = 16; off > 0; off >>= 1)
        v += __shfl_down_sync(0xFFFFFFFFu, v, off);
    return v;
}

__global__ void __launch_bounds__(THREADS)
station_loss_kernel(const float* __restrict__ pred,
                    const int*   __restrict__ pos,
                    const float* __restrict__ runoff,
                    float*       __restrict__ out)
{
    int idx = blockIdx.x * THREADS + threadIdx.x;   // exact grid, no bounds check
    unsigned long long pol = make_evict_last_policy();

    int b  = idx / SS;
    int2 p = ldg_el_i2(reinterpret_cast<const int2*>(pos) + idx, pol);
    int px = p.x;   // width index
    int py = p.y;   // height index

    const float* base = pred + (size_t)b * (size_t)(HH * WW);
    float avg;

    if (px >= 1 && px <= WW - 2 && py >= 1 && py <= HH - 2) {
        // Fast path (~99.8%): all 9 taps valid, cnt = 9.
        int a4  = (px - 1) >> 2;
        int off = (px - 1) & 3;
        float s0 = row_sum3(base + (size_t)(py - 1) * WW, a4, off, pol);
        float s1 = row_sum3(base + (size_t)(py    ) * WW, a4, off, pol);
        float s2 = row_sum3(base + (size_t)(py + 1) * WW, a4, off, pol);
        avg = (s0 + s1 + s2) * (1.0f / 9.0f);
    } else {
        // Edge path (rare): masked 9-tap with clamped coords.
        float sum = 0.0f, cnt = 0.0f;
        #pragma unroll
        for (int dy = -1; dy <= 1; ++dy) {
            int y   = py + dy;
            bool vy = (y >= 0) & (y < HH);
            int yc  = min(max(y, 0), HH - 1);
            const float* row = base + (size_t)yc * WW;
            #pragma unroll
            for (int dx = -1; dx <= 1; ++dx) {
                int x  = px + dx;
                bool v = vy & (x >= 0) & (x < WW);
                int xc = min(max(x, 0), WW - 1);
                float val = ldg_el_f(row + xc, pol);
                sum += v ? val  : 0.0f;
                cnt += v ? 1.0f : 0.0f;
            }
        }
        avg = sum / cnt;
    }

    float d    = avg - ldg_el_f(runoff + idx, pol);
    float err2 = d * d;

    // Deterministic block reduction: warp shuffle then fixed-order sum of 10.
    __shared__ float warp_sums[NWARP];
    err2 = warp_reduce(err2);

    int lane = threadIdx.x & 31;
    int wid  = threadIdx.x >> 5;
    if (lane == 0) warp_sums[wid] = err2;
    __syncthreads();

    __shared__ bool is_last;
    if (threadIdx.x == 0) {
        float v = 0.0f;
        #pragma unroll
        for (int i = 0; i < NWARP; ++i)
            v += warp_sums[i];
        g_partials[blockIdx.x] = v;
        unsigned done = atomic_inc_acqrel(&g_count);   // release orders the store
        is_last = (done == NBLK - 1);
    }
    __syncthreads();

    // Last block: deterministic final reduction over 250 partials.
    if (is_last) {
        float v = 0.0f;
        for (int i = threadIdx.x; i < NBLK; i += THREADS)
            v += __ldcg(&g_partials[i]);
        v = warp_reduce(v);

        __shared__ float fin[NWARP];
        if (lane == 0) fin[wid] = v;
        __syncthreads();
        if (threadIdx.x == 0) {
            float s = 0.0f;
            #pragma unroll
            for (int i = 0; i < NWARP; ++i)
                s += fin[i];
            out[0]  = s / (float)TOTAL;
            g_count = 0u;   // re-arm for next graph replay
        }
    }
}

extern "C" void kernel_launch(void* const* d_in, const int* in_sizes, int n_in,
                              void* d_out, int out_size)
{
    const float* pred   = (const float*)d_in[0];  // (B,1,H,W) f32
    const int*   pos    = (const int*)  d_in[1];  // (B,S,2)  i32
    const float* runoff = (const float*)d_in[2];  // (B,S)    f32
    float* out = (float*)d_out;

    station_loss_kernel<<<NBLK, THREADS>>>(pred, pos, runoff, out);
}